// round 5
// baseline (speedup 1.0000x reference)
#include <cuda_runtime.h>
#include <math.h>

// Problem constants (fixed by the dataset)
#define NX 8192
#define NY 16384
#define KD 512
#define TOPK 16
#define CAND 32      // candidates kept per row (by sim value)

#define BM 32        // X rows per block
#define BN 128       // Y rows per chunk
#define BK 32        // K chunk
#define THREADS 256
#define SIMLD 129    // padded sim row stride -> conflict-free strided column reads

#define NEG_INF __int_as_float(0xff800000)

// exp(d) flushes (FTZ) / clamps to the tie block for d <= this float:
// boundary is ln(2^-126) = -87.3365447505...; for float d the condition
// "exp(d) >= 2^-126" is exactly "d > -87.3365478515625f".
#define EXP_LO   -87.3365478515625f
#define FLT_MIN_F 1.17549435082228751e-38f   // 2^-126, smallest normal

__global__ __launch_bounds__(THREADS, 2)
void snf_kernel(const float* __restrict__ X, const float* __restrict__ Y,
                float* __restrict__ out)
{
    __shared__ float Xs[BK][BM];          // [k][m]
    __shared__ float Ys[BK][BN];          // [k][n]
    __shared__ float sim[BM][SIMLD];      // padded
    __shared__ float cv[CAND][BM];        // candidate values, sorted desc per row
    __shared__ int   ci[CAND][BM];        // candidate indices

    const int tid  = threadIdx.x;
    const int warp = tid >> 5;
    const int lane = tid & 31;
    const int row0 = blockIdx.x * BM;

    for (int i = tid; i < CAND * BM; i += THREADS) {
        cv[i / BM][i % BM] = NEG_INF;
        ci[i / BM][i % BM] = 0;
    }

    const int mi = warp * 4;         // m sub-block (0..28)
    const int ni = lane * 4;         // n sub-block (0..124)

    for (int jt = 0; jt < NY; jt += BN) {
        float acc[4][4];
        #pragma unroll
        for (int a = 0; a < 4; a++)
            #pragma unroll
            for (int b = 0; b < 4; b++) acc[a][b] = 0.0f;

        // k strictly ascending, single fp32 FMA accumulator per output —
        // bit-matches a sequential-k fp32 GEMM (cublas sgemm / Eigen gebp).
        for (int kt = 0; kt < KD; kt += BK) {
            {
                int m  = tid & 31;
                int kq = (tid >> 5) * 4;
                float4 v = *(const float4*)&X[(size_t)(row0 + m) * KD + kt + kq];
                Xs[kq + 0][m] = v.x; Xs[kq + 1][m] = v.y;
                Xs[kq + 2][m] = v.z; Xs[kq + 3][m] = v.w;
            }
            #pragma unroll
            for (int i = 0; i < 4; i++) {
                int f  = tid + i * THREADS;
                int n  = f & 127;
                int kq = (f >> 7) * 4;
                float4 v = *(const float4*)&Y[(size_t)(jt + n) * KD + kt + kq];
                Ys[kq + 0][n] = v.x; Ys[kq + 1][n] = v.y;
                Ys[kq + 2][n] = v.z; Ys[kq + 3][n] = v.w;
            }
            __syncthreads();

            #pragma unroll
            for (int kk = 0; kk < BK; kk++) {
                float4 a4 = *(const float4*)&Xs[kk][mi];
                float4 b4 = *(const float4*)&Ys[kk][ni];
                float am[4] = {a4.x, a4.y, a4.z, a4.w};
                float bn[4] = {b4.x, b4.y, b4.z, b4.w};
                #pragma unroll
                for (int a = 0; a < 4; a++)
                    #pragma unroll
                    for (int b = 0; b < 4; b++)
                        acc[a][b] = fmaf(am[a], bn[b], acc[a][b]);
            }
            __syncthreads();
        }

        // elementwise fp32 division by TAU, same op as reference
        #pragma unroll
        for (int a = 0; a < 4; a++)
            #pragma unroll
            for (int b = 0; b < 4; b++)
                sim[mi + a][ni + b] = __fdiv_rn(acc[a][b], 0.07f);
        __syncthreads();

        // candidate scan: warp w owns rows 4w..4w+3 (ballot, rare inserts)
        #pragma unroll
        for (int rr = 0; rr < 4; rr++) {
            const int r = warp * 4 + rr;
            float v[4]; int jj[4];
            #pragma unroll
            for (int c = 0; c < 4; c++) {
                v[c]  = sim[r][lane + c * 32];
                jj[c] = jt + lane + c * 32;
            }
            while (true) {
                float thr = cv[CAND - 1][r];
                bool any = (v[0] > thr) | (v[1] > thr) | (v[2] > thr) | (v[3] > thr);
                if (!__ballot_sync(0xffffffffu, any)) break;
                float bmv = NEG_INF; int bj = 0x7fffffff;
                #pragma unroll
                for (int c = 0; c < 4; c++)
                    if (v[c] > thr && (v[c] > bmv || (v[c] == bmv && jj[c] < bj))) {
                        bmv = v[c]; bj = jj[c];
                    }
                #pragma unroll
                for (int off = 16; off > 0; off >>= 1) {
                    float ov = __shfl_xor_sync(0xffffffffu, bmv, off);
                    int   oj = __shfl_xor_sync(0xffffffffu, bj,  off);
                    if (ov > bmv || (ov == bmv && oj < bj)) { bmv = ov; bj = oj; }
                }
                if (lane == 0) {
                    int p = CAND - 1;
                    while (p > 0 && bmv > cv[p - 1][r]) {
                        cv[p][r] = cv[p - 1][r];
                        ci[p][r] = ci[p - 1][r];
                        p--;
                    }
                    cv[p][r] = bmv; ci[p][r] = bj;
                }
                __syncwarp();
                #pragma unroll
                for (int c = 0; c < 4; c++)
                    if (v[c] == bmv && jj[c] == bj) v[c] = NEG_INF;   // consume
            }
        }
        __syncthreads();
    }

    // ---- epilogue: FTZ softmax semantics ----
    // e = exp(s - M): flushed to 0 if result subnormal      (exp-site FTZ/clamp)
    // P = e / S:      flushed to 0 if quotient subnormal    (division-site FTZ)
    // head = candidates with P > 0, ranked by P desc (== sim desc);
    // tail = the all-zero tie block -> ascending indices (lax.top_k stability).
    if (tid < BM) {
        const int r = tid;
        const float M = cv[0][r];   // exact fp32 row max

        float ef[CAND];
        float S = 0.0f;
        #pragma unroll
        for (int c = 0; c < CAND; c++) {
            float d = cv[c][r] - M;             // fp32 subtract, as reference
            float e = 0.0f;
            if (cv[c][r] != NEG_INF && d > EXP_LO) {
                e = __double2float_rn(exp((double)d));
                if (e < FLT_MIN_F) e = 0.0f;    // exp output would be subnormal
            }
            ef[c] = e;
            S += e;                             // fp32; zeros elsewhere in the row
        }

        int outv[TOPK];
        int cnt = 0;
        for (int c = 0; c < CAND && cnt < TOPK; c++) {
            if (ef[c] > 0.0f) {
                float q = __fdiv_rn(ef[c], S);
                if (q >= FLT_MIN_F)             // survives division FTZ -> head
                    outv[cnt++] = ci[c][r];
            }
        }
        const int nz = cnt;

        // tail: P == 0 ties -> ascending indices, skipping emitted ones
        for (int j = 0; cnt < TOPK; j++) {
            bool used = false;
            for (int q2 = 0; q2 < nz; q2++)
                if (outv[q2] == j) { used = true; break; }
            if (!used) outv[cnt++] = j;
        }

        #pragma unroll
        for (int k = 0; k < TOPK; k++)
            out[(size_t)(row0 + r) * TOPK + k] = (float)outv[k];   // float32 output
    }
}

extern "C" void kernel_launch(void* const* d_in, const int* in_sizes, int n_in,
                              void* d_out, int out_size)
{
    const float* X = (const float*)d_in[0];   // [8192, 512]
    const float* Y = (const float*)d_in[1];   // [16384, 512]
    if (n_in >= 2 && in_sizes[0] == NY * KD && in_sizes[1] == NX * KD) {
        X = (const float*)d_in[1];
        Y = (const float*)d_in[0];
    }
    float* out = (float*)d_out;               // [8192, 16] as float32
    (void)out_size;

    snf_kernel<<<NX / BM, THREADS>>>(X, Y, out);
}

// round 7
// speedup vs baseline: 1.7838x; 1.7838x over previous
#include <cuda_runtime.h>
#include <math.h>
#include <stdint.h>

#define NX 8192
#define NY 16384
#define KD 512
#define TOPK 16
#define CAND 32

#define BM 64        // X rows per block
#define BN 128       // Y rows per chunk
#define BK 32        // staged K chunk
#define THREADS 256

#define XSLD 516     // Xs row stride (floats): 516%32==4 -> conflict-free A frags
#define YSLD 136     // Ys row stride (floats): 136%32==8 -> conflict-free B frags
#define SIMLD 129

#define NEG_INF __int_as_float(0xff800000)
#define EXP_LO   -87.3365478515625f
#define FLT_MIN_F 1.17549435082228751e-38f

// dynamic smem layout (floats)
#define OFF_XS   0
#define OFF_YS   (BM * XSLD)                    // 33024
#define OFF_SIM  (OFF_YS + BK * YSLD)           // +4352
#define OFF_CV   (OFF_SIM + BM * SIMLD)         // +8256
#define OFF_CI   (OFF_CV + CAND * BM)           // +2048
#define SMEM_FLOATS (OFF_CI + CAND * BM)
#define SMEM_BYTES  (SMEM_FLOATS * 4)           // 198912 B

__device__ __forceinline__ void mma_tf32(float c[4], const uint32_t a[4],
                                         uint32_t b0, uint32_t b1)
{
    asm volatile(
        "mma.sync.aligned.m16n8k8.row.col.f32.tf32.tf32.f32 "
        "{%0,%1,%2,%3}, {%4,%5,%6,%7}, {%8,%9}, {%0,%1,%2,%3};"
        : "+f"(c[0]), "+f"(c[1]), "+f"(c[2]), "+f"(c[3])
        : "r"(a[0]), "r"(a[1]), "r"(a[2]), "r"(a[3]), "r"(b0), "r"(b1));
}

__global__ __launch_bounds__(THREADS)
void snf_kernel(const float* __restrict__ X, const float* __restrict__ Y,
                float* __restrict__ out)
{
    extern __shared__ float smem[];
    float* Xs  = smem + OFF_XS;    // [BM][XSLD] exact fp32 X tile (whole K)
    float* Ys  = smem + OFF_YS;    // [BK][YSLD]
    float* sim = smem + OFF_SIM;   // [BM][SIMLD] approx sims
    float* cv  = smem + OFF_CV;    // [CAND][BM]
    int*   ci  = (int*)(smem + OFF_CI);

    const int tid  = threadIdx.x;
    const int warp = tid >> 5;
    const int lane = tid & 31;
    const int g    = lane >> 2;   // groupID (0..7)
    const int t    = lane & 3;    // thread-in-group (0..3)
    const int mw   = warp & 1;    // m half (0..1), 32 rows each
    const int nw   = warp >> 1;   // n quarter (0..3), 32 cols each
    const int row0 = blockIdx.x * BM;

    // ---- load whole X tile (BM x KD) into smem once ----
    #pragma unroll
    for (int i = 0; i < 32; i++) {
        int f  = tid + i * THREADS;            // float4 index, 0..8191
        int r  = f >> 7;                       // 128 float4 per row
        int kq = (f & 127) * 4;
        float4 v = *(const float4*)&X[(size_t)(row0 + r) * KD + kq];
        *(float4*)&Xs[r * XSLD + kq] = v;
    }
    for (int i = tid; i < CAND * BM; i += THREADS) {
        cv[i] = NEG_INF;
        ci[i] = 0;
    }
    __syncthreads();

    for (int jt = 0; jt < NY; jt += BN) {
        float acc[2][4][4];
        #pragma unroll
        for (int mt = 0; mt < 2; mt++)
            #pragma unroll
            for (int nt = 0; nt < 4; nt++)
                #pragma unroll
                for (int q = 0; q < 4; q++) acc[mt][nt][q] = 0.0f;

        for (int kt = 0; kt < KD; kt += BK) {
            // stage Y chunk (BN x BK) as [k][n]
            #pragma unroll
            for (int i = 0; i < 4; i++) {
                int f  = tid + i * THREADS;
                int n  = f & 127;
                int kq = (f >> 7) * 4;
                float4 v = *(const float4*)&Y[(size_t)(jt + n) * KD + kt + kq];
                Ys[(kq + 0) * YSLD + n] = v.x;
                Ys[(kq + 1) * YSLD + n] = v.y;
                Ys[(kq + 2) * YSLD + n] = v.z;
                Ys[(kq + 3) * YSLD + n] = v.w;
            }
            __syncthreads();

            #pragma unroll
            for (int ks = 0; ks < 4; ks++) {
                const int kb = kt + ks * 8;
                uint32_t a[2][4];
                #pragma unroll
                for (int mt = 0; mt < 2; mt++) {
                    int m = mw * 32 + mt * 16 + g;
                    a[mt][0] = __float_as_uint(Xs[(m + 0) * XSLD + kb + t]);
                    a[mt][1] = __float_as_uint(Xs[(m + 8) * XSLD + kb + t]);
                    a[mt][2] = __float_as_uint(Xs[(m + 0) * XSLD + kb + t + 4]);
                    a[mt][3] = __float_as_uint(Xs[(m + 8) * XSLD + kb + t + 4]);
                }
                #pragma unroll
                for (int nt = 0; nt < 4; nt++) {
                    int n = nw * 32 + nt * 8 + g;
                    int kk = ks * 8 + t;
                    uint32_t b0 = __float_as_uint(Ys[(kk + 0) * YSLD + n]);
                    uint32_t b1 = __float_as_uint(Ys[(kk + 4) * YSLD + n]);
                    mma_tf32(acc[0][nt], a[0], b0, b1);
                    mma_tf32(acc[1][nt], a[1], b0, b1);
                }
            }
            __syncthreads();
        }

        // ---- dump approx sims (un-divided; ranking is scale-invariant) ----
        #pragma unroll
        for (int mt = 0; mt < 2; mt++)
            #pragma unroll
            for (int nt = 0; nt < 4; nt++) {
                int r0 = mw * 32 + mt * 16 + g;
                int c0 = nw * 32 + nt * 8 + 2 * t;
                sim[(r0 + 0) * SIMLD + c0 + 0] = acc[mt][nt][0];
                sim[(r0 + 0) * SIMLD + c0 + 1] = acc[mt][nt][1];
                sim[(r0 + 8) * SIMLD + c0 + 0] = acc[mt][nt][2];
                sim[(r0 + 8) * SIMLD + c0 + 1] = acc[mt][nt][3];
            }
        __syncthreads();

        // ---- candidate scan on approx sims: warp w owns rows 8w..8w+7 ----
        #pragma unroll
        for (int rr = 0; rr < 8; rr++) {
            const int r = warp * 8 + rr;
            float v[4]; int jj[4];
            #pragma unroll
            for (int c = 0; c < 4; c++) {
                v[c]  = sim[r * SIMLD + lane + c * 32];
                jj[c] = jt + lane + c * 32;
            }
            while (true) {
                float thr = cv[(CAND - 1) * BM + r];
                bool any = (v[0] > thr) | (v[1] > thr) | (v[2] > thr) | (v[3] > thr);
                if (!__ballot_sync(0xffffffffu, any)) break;
                float bmv = NEG_INF; int bj = 0x7fffffff;
                #pragma unroll
                for (int c = 0; c < 4; c++)
                    if (v[c] > thr && (v[c] > bmv || (v[c] == bmv && jj[c] < bj))) {
                        bmv = v[c]; bj = jj[c];
                    }
                #pragma unroll
                for (int off = 16; off > 0; off >>= 1) {
                    float ov = __shfl_xor_sync(0xffffffffu, bmv, off);
                    int   oj = __shfl_xor_sync(0xffffffffu, bj,  off);
                    if (ov > bmv || (ov == bmv && oj < bj)) { bmv = ov; bj = oj; }
                }
                if (lane == 0) {
                    int p = CAND - 1;
                    while (p > 0 && bmv > cv[(p - 1) * BM + r]) {
                        cv[p * BM + r] = cv[(p - 1) * BM + r];
                        ci[p * BM + r] = ci[(p - 1) * BM + r];
                        p--;
                    }
                    cv[p * BM + r] = bmv; ci[p * BM + r] = bj;
                }
                __syncwarp();
                #pragma unroll
                for (int c = 0; c < 4; c++)
                    if (v[c] == bmv && jj[c] == bj) v[c] = NEG_INF;
            }
        }
        __syncthreads();
    }

    // ---- EXACT rescore of all candidates: sequential-k fp32 fmaf chain,
    //      bit-identical to the reference sgemm, then fp32 divide by TAU ----
    {
        float accd[8];
        int   rD[8], cD[8];
        const float* yp[8];
        #pragma unroll
        for (int d = 0; d < 8; d++) {
            int idx = tid + d * THREADS;       // 0..2047
            rD[d] = idx >> 5;
            cD[d] = idx & 31;
            yp[d] = &Y[(size_t)ci[cD[d] * BM + rD[d]] * KD];
            accd[d] = 0.0f;
        }
        for (int k = 0; k < KD; k += 4) {
            #pragma unroll
            for (int d = 0; d < 8; d++) {
                float4 x4 = *(const float4*)&Xs[rD[d] * XSLD + k];
                float4 y4 = __ldg((const float4*)(yp[d] + k));
                float a = accd[d];
                a = fmaf(x4.x, y4.x, a);
                a = fmaf(x4.y, y4.y, a);
                a = fmaf(x4.z, y4.z, a);
                a = fmaf(x4.w, y4.w, a);
                accd[d] = a;
            }
        }
        __syncthreads();   // all scan reads of cv done before overwrite
        #pragma unroll
        for (int d = 0; d < 8; d++)
            cv[cD[d] * BM + rD[d]] = __fdiv_rn(accd[d], 0.07f);
    }
    __syncthreads();

    // ---- exact FTZ-softmax epilogue (identical to the round-5 passing rule) ----
    if (tid < BM) {
        const int r = tid;

        float pv[CAND]; int id[CAND];
        #pragma unroll
        for (int c = 0; c < CAND; c++) { pv[c] = cv[c * BM + r]; id[c] = ci[c * BM + r]; }

        // exact sort: value desc, index asc (approx order may be slightly off)
        for (int i = 1; i < CAND; i++) {
            float kp = pv[i]; int kd = id[i];
            int j2 = i - 1;
            while (j2 >= 0 && (pv[j2] < kp || (pv[j2] == kp && id[j2] > kd))) {
                pv[j2 + 1] = pv[j2]; id[j2 + 1] = id[j2];
                j2--;
            }
            pv[j2 + 1] = kp; id[j2 + 1] = kd;
        }

        const float M = pv[0];
        float ef[CAND]; float S = 0.0f;
        #pragma unroll
        for (int c = 0; c < CAND; c++) {
            float d = pv[c] - M;
            float e = 0.0f;
            if (d > EXP_LO) {
                e = __double2float_rn(exp((double)d));
                if (e < FLT_MIN_F) e = 0.0f;
            }
            ef[c] = e;
            S += e;
        }

        int outv[TOPK]; int cnt = 0;
        for (int c = 0; c < CAND && cnt < TOPK; c++) {
            if (ef[c] > 0.0f) {
                float q = __fdiv_rn(ef[c], S);
                if (q >= FLT_MIN_F) outv[cnt++] = id[c];
            }
        }
        const int nz = cnt;
        for (int j = 0; cnt < TOPK; j++) {
            bool used = false;
            for (int q2 = 0; q2 < nz; q2++)
                if (outv[q2] == j) { used = true; break; }
            if (!used) outv[cnt++] = j;
        }

        #pragma unroll
        for (int k = 0; k < TOPK; k++)
            out[(size_t)(row0 + r) * TOPK + k] = (float)outv[k];
    }
}

extern "C" void kernel_launch(void* const* d_in, const int* in_sizes, int n_in,
                              void* d_out, int out_size)
{
    const float* X = (const float*)d_in[0];
    const float* Y = (const float*)d_in[1];
    if (n_in >= 2 && in_sizes[0] == NY * KD && in_sizes[1] == NX * KD) {
        X = (const float*)d_in[1];
        Y = (const float*)d_in[0];
    }
    float* out = (float*)d_out;
    (void)out_size;

    static int attr_set = 0;
    if (!attr_set) {
        cudaFuncSetAttribute(snf_kernel, cudaFuncAttributeMaxDynamicSharedMemorySize,
                             SMEM_BYTES);
        attr_set = 1;
    }
    snf_kernel<<<NX / BM, THREADS, SMEM_BYTES>>>(X, Y, out);
}

// round 8
// speedup vs baseline: 2.7522x; 1.5428x over previous
#include <cuda_runtime.h>
#include <cuda_bf16.h>
#include <math.h>
#include <stdint.h>

#define NX 8192
#define NY 16384
#define KD 512
#define TOPK 16
#define CAND 28

#define BM 64
#define BN 128
#define BK 32
#define THREADS 256
#define NSTAGE_PER_JT 16                    // KD/BK
#define TOTAL_STAGES ((NY / BN) * NSTAGE_PER_JT)   // 2048

#define NEG_INF __int_as_float(0xff800000)
#define EXP_LO   -87.3365478515625f
#define FLT_MIN_F 1.17549435082228751e-38f

// ---- smem byte layout (total 115,200 B -> 2 CTAs/SM) ----
#define OFF_XS_B   0            // bf16 Xs [64][520 halves]         = 66,560
#define OFF_YS_B   66560        // bf16 Ys [2][128][40 halves]      = 20,480
#define OFF_SIM_B  87040        // bf16 sim [64][136 halves]        = 17,408  (reused as fp32 rv)
#define OFF_CV_B   104448       // bf16 cv  [CAND][64]              =  3,584
#define OFF_CI_B   108032       // int  ci  [CAND][64]              =  7,168
#define SMEM_BYTES 115200

#define XS_WSTRIDE 260   // words per Xs row (520 halves)
#define YS_WSTRIDE 20    // words per Ys row (40 halves)
#define YS_STAGE_B 10240 // bytes per Ys stage
#define SIM_WSTRIDE 68   // words per sim row (136 halves)
#define SIM_HSTRIDE 136

// pre-converted bf16 copies (static device globals: allowed scratch)
__device__ __nv_bfloat16 g_Xbf[(size_t)NX * KD];
__device__ __nv_bfloat16 g_Ybf[(size_t)NY * KD];

__global__ __launch_bounds__(256)
void cvt_kernel(const float* __restrict__ X, const float* __restrict__ Y)
{
    const size_t NXF4 = (size_t)NX * KD / 4;   // 1,048,576
    const size_t NYF4 = (size_t)NY * KD / 4;   // 2,097,152
    size_t i = (size_t)blockIdx.x * blockDim.x + threadIdx.x;
    if (i < NXF4) {
        float4 v = ((const float4*)X)[i];
        __nv_bfloat162 lo = __floats2bfloat162_rn(v.x, v.y);
        __nv_bfloat162 hi = __floats2bfloat162_rn(v.z, v.w);
        uint2 u = make_uint2(*(uint32_t*)&lo, *(uint32_t*)&hi);
        *(uint2*)&g_Xbf[i * 4] = u;
    } else if (i < NXF4 + NYF4) {
        size_t j = i - NXF4;
        float4 v = ((const float4*)Y)[j];
        __nv_bfloat162 lo = __floats2bfloat162_rn(v.x, v.y);
        __nv_bfloat162 hi = __floats2bfloat162_rn(v.z, v.w);
        uint2 u = make_uint2(*(uint32_t*)&lo, *(uint32_t*)&hi);
        *(uint2*)&g_Ybf[j * 4] = u;
    }
}

__device__ __forceinline__ uint32_t smem_u32(const void* p) {
    uint32_t a;
    asm("{ .reg .u64 t; cvta.to.shared.u64 t, %1; cvt.u32.u64 %0, t; }"
        : "=r"(a) : "l"(p));
    return a;
}

__device__ __forceinline__ void cp16(uint32_t dst, const void* src) {
    asm volatile("cp.async.cg.shared.global [%0], [%1], 16;\n"
                 :: "r"(dst), "l"(src) : "memory");
}

__device__ __forceinline__ void hmma(float c[4], const uint32_t a[4],
                                     uint32_t b0, uint32_t b1)
{
    asm volatile(
        "mma.sync.aligned.m16n8k16.row.col.f32.bf16.bf16.f32 "
        "{%0,%1,%2,%3}, {%4,%5,%6,%7}, {%8,%9}, {%0,%1,%2,%3};"
        : "+f"(c[0]), "+f"(c[1]), "+f"(c[2]), "+f"(c[3])
        : "r"(a[0]), "r"(a[1]), "r"(a[2]), "r"(a[3]), "r"(b0), "r"(b1));
}

__global__ __launch_bounds__(THREADS, 2)
void snf_kernel(const float* __restrict__ X, const float* __restrict__ Y,
                float* __restrict__ out)
{
    extern __shared__ __align__(16) char smem[];
    uint32_t*       XsW  = (uint32_t*)(smem + OFF_XS_B);
    uint32_t*       simW = (uint32_t*)(smem + OFF_SIM_B);
    __nv_bfloat16*  simH = (__nv_bfloat16*)(smem + OFF_SIM_B);
    float*          rv   = (float*)(smem + OFF_SIM_B);        // after scan: rescored fp32
    __nv_bfloat16*  cvH  = (__nv_bfloat16*)(smem + OFF_CV_B);
    int*            ci   = (int*)(smem + OFF_CI_B);

    const int tid  = threadIdx.x;
    const int warp = tid >> 5;
    const int lane = tid & 31;
    const int g    = lane >> 2;
    const int t    = lane & 3;
    const int mw   = warp & 1;
    const int nw   = warp >> 1;
    const int row0 = blockIdx.x * BM;
    const uint32_t sbase = smem_u32(smem);

    // ---- prologue: issue cp.async for stage 0 immediately ----
    {
        #pragma unroll
        for (int s2 = 0; s2 < 2; s2++) {
            int f = tid + s2 * THREADS;
            int n = f >> 2, c = f & 3;
            uint32_t dst = sbase + OFF_YS_B + n * 80 + c * 16;
            const void* src = (const void*)(g_Ybf + (size_t)n * KD + c * 8);
            cp16(dst, src);
        }
        asm volatile("cp.async.commit_group;" ::: "memory");
    }

    // ---- fill bf16 Xs tile from g_Xbf (whole K) ----
    {
        const uint4* xsrc = (const uint4*)(g_Xbf + (size_t)row0 * KD);
        #pragma unroll
        for (int i = 0; i < 16; i++) {
            int f = tid + i * THREADS;   // 0..4095
            int m = f >> 6, c = f & 63;
            *(uint4*)(smem + OFF_XS_B + m * 1040 + c * 16) = xsrc[m * 64 + c];
        }
    }
    for (int i = tid; i < CAND * BM; i += THREADS) {
        cvH[i] = __ushort_as_bfloat16(0xFF80);   // -inf
        ci[i]  = 0;
    }

    float acc[2][4][4];

    for (int S = 0; S < TOTAL_STAGES; S++) {
        // ---- issue stage S+1 into buffer (S+1)&1 ----
        if (S + 1 < TOTAL_STAGES) {
            int jt1 = ((S + 1) >> 4) * BN;
            int kt1 = ((S + 1) & 15) * BK;
            uint32_t ybase = sbase + OFF_YS_B + ((S + 1) & 1) * YS_STAGE_B;
            #pragma unroll
            for (int s2 = 0; s2 < 2; s2++) {
                int f = tid + s2 * THREADS;
                int n = f >> 2, c = f & 3;
                cp16(ybase + n * 80 + c * 16,
                     (const void*)(g_Ybf + (size_t)(jt1 + n) * KD + kt1 + c * 8));
            }
        }
        asm volatile("cp.async.commit_group;" ::: "memory");
        asm volatile("cp.async.wait_group 1;" ::: "memory");
        __syncthreads();

        // ---- compute stage S from buffer S&1 ----
        const uint32_t* YsW = (const uint32_t*)(smem + OFF_YS_B + (S & 1) * YS_STAGE_B);
        const int kb2 = (S & 15) * (BK / 2);   // word offset of this stage's k in Xs

        if ((S & 15) == 0) {
            #pragma unroll
            for (int mt = 0; mt < 2; mt++)
                #pragma unroll
                for (int nt = 0; nt < 4; nt++)
                    #pragma unroll
                    for (int q = 0; q < 4; q++) acc[mt][nt][q] = 0.0f;
        }

        #pragma unroll
        for (int ks = 0; ks < 2; ks++) {
            const int kw = ks * 8;
            uint32_t a[2][4];
            #pragma unroll
            for (int mt = 0; mt < 2; mt++) {
                int m = mw * 32 + mt * 16 + g;
                a[mt][0] = XsW[(m + 0) * XS_WSTRIDE + kb2 + kw + t];
                a[mt][1] = XsW[(m + 8) * XS_WSTRIDE + kb2 + kw + t];
                a[mt][2] = XsW[(m + 0) * XS_WSTRIDE + kb2 + kw + t + 4];
                a[mt][3] = XsW[(m + 8) * XS_WSTRIDE + kb2 + kw + t + 4];
            }
            #pragma unroll
            for (int nt = 0; nt < 4; nt++) {
                int n = nw * 32 + nt * 8 + g;
                uint32_t b0 = YsW[n * YS_WSTRIDE + kw + t];
                uint32_t b1 = YsW[n * YS_WSTRIDE + kw + t + 4];
                hmma(acc[0][nt], a[0], b0, b1);
                hmma(acc[1][nt], a[1], b0, b1);
            }
        }

        if ((S & 15) == 15) {
            const int jt = (S >> 4) * BN;
            // ---- dump approx sims as bf16 pairs ----
            #pragma unroll
            for (int mt = 0; mt < 2; mt++)
                #pragma unroll
                for (int nt = 0; nt < 4; nt++) {
                    int r0 = mw * 32 + mt * 16 + g;
                    int c0 = nw * 32 + nt * 8 + 2 * t;
                    __nv_bfloat162 p0 = __floats2bfloat162_rn(acc[mt][nt][0], acc[mt][nt][1]);
                    __nv_bfloat162 p1 = __floats2bfloat162_rn(acc[mt][nt][2], acc[mt][nt][3]);
                    simW[(r0 + 0) * SIM_WSTRIDE + (c0 >> 1)] = *(uint32_t*)&p0;
                    simW[(r0 + 8) * SIM_WSTRIDE + (c0 >> 1)] = *(uint32_t*)&p1;
                }
            __syncthreads();

            // ---- candidate scan: warp w owns rows 8w..8w+7 ----
            #pragma unroll
            for (int rr = 0; rr < 8; rr++) {
                const int r = warp * 8 + rr;
                float v[4]; int jj[4];
                #pragma unroll
                for (int c = 0; c < 4; c++) {
                    v[c]  = __bfloat162float(simH[r * SIM_HSTRIDE + lane + c * 32]);
                    jj[c] = jt + lane + c * 32;
                }
                while (true) {
                    float thr = __bfloat162float(cvH[(CAND - 1) * BM + r]);
                    bool any = (v[0] > thr) | (v[1] > thr) | (v[2] > thr) | (v[3] > thr);
                    if (!__ballot_sync(0xffffffffu, any)) break;
                    float bmv = NEG_INF; int bj = 0x7fffffff;
                    #pragma unroll
                    for (int c = 0; c < 4; c++)
                        if (v[c] > thr && (v[c] > bmv || (v[c] == bmv && jj[c] < bj))) {
                            bmv = v[c]; bj = jj[c];
                        }
                    #pragma unroll
                    for (int off = 16; off > 0; off >>= 1) {
                        float ov = __shfl_xor_sync(0xffffffffu, bmv, off);
                        int   oj = __shfl_xor_sync(0xffffffffu, bj,  off);
                        if (ov > bmv || (ov == bmv && oj < bj)) { bmv = ov; bj = oj; }
                    }
                    if (lane == 0) {
                        int p = CAND - 1;
                        while (p > 0 && bmv > __bfloat162float(cvH[(p - 1) * BM + r])) {
                            cvH[p * BM + r] = cvH[(p - 1) * BM + r];
                            ci[p * BM + r]  = ci[(p - 1) * BM + r];
                            p--;
                        }
                        cvH[p * BM + r] = __float2bfloat16_rn(bmv);
                        ci[p * BM + r]  = bj;
                    }
                    __syncwarp();
                    #pragma unroll
                    for (int c = 0; c < 4; c++)
                        if (v[c] == bmv && jj[c] == bj) v[c] = NEG_INF;
                }
            }
        }
        __syncthreads();   // also protects Ys buffer reuse by next issue
    }

    // ---- EXACT rescore: sequential-k fp32 fmaf chain (bit-identical to ref) ----
    {
        float accd[7];
        int   rD[7], cD[7];
        const float* yp[7];
        #pragma unroll
        for (int d = 0; d < 7; d++) {
            int idx = tid + d * THREADS;        // 0..1791 = CAND*BM - 1
            rD[d] = idx / CAND;
            cD[d] = idx % CAND;
            yp[d] = &Y[(size_t)ci[cD[d] * BM + rD[d]] * KD];
            accd[d] = 0.0f;
        }
        for (int k = 0; k < KD; k += 4) {
            #pragma unroll
            for (int d = 0; d < 7; d++) {
                float4 x4 = __ldg((const float4*)&X[(size_t)(row0 + rD[d]) * KD + k]);
                float4 y4 = __ldg((const float4*)(yp[d] + k));
                float a = accd[d];
                a = fmaf(x4.x, y4.x, a);
                a = fmaf(x4.y, y4.y, a);
                a = fmaf(x4.z, y4.z, a);
                a = fmaf(x4.w, y4.w, a);
                accd[d] = a;
            }
        }
        __syncthreads();   // all scan reads done; sim area becomes rv
        #pragma unroll
        for (int d = 0; d < 7; d++)
            rv[cD[d] * BM + rD[d]] = __fdiv_rn(accd[d], 0.07f);
    }
    __syncthreads();

    // ---- exact FTZ-softmax epilogue (unchanged passing rule) ----
    if (tid < BM) {
        const int r = tid;

        float pv[CAND]; int id[CAND];
        #pragma unroll
        for (int c = 0; c < CAND; c++) { pv[c] = rv[c * BM + r]; id[c] = ci[c * BM + r]; }

        for (int i = 1; i < CAND; i++) {
            float kp = pv[i]; int kd = id[i];
            int j2 = i - 1;
            while (j2 >= 0 && (pv[j2] < kp || (pv[j2] == kp && id[j2] > kd))) {
                pv[j2 + 1] = pv[j2]; id[j2 + 1] = id[j2];
                j2--;
            }
            pv[j2 + 1] = kp; id[j2 + 1] = kd;
        }

        const float M = pv[0];
        float ef[CAND]; float S = 0.0f;
        #pragma unroll
        for (int c = 0; c < CAND; c++) {
            float d = pv[c] - M;
            float e = 0.0f;
            if (d > EXP_LO) {
                e = __double2float_rn(exp((double)d));
                if (e < FLT_MIN_F) e = 0.0f;
            }
            ef[c] = e;
            S += e;
        }

        int outv[TOPK]; int cnt = 0;
        for (int c = 0; c < CAND && cnt < TOPK; c++) {
            if (ef[c] > 0.0f) {
                float q = __fdiv_rn(ef[c], S);
                if (q >= FLT_MIN_F) outv[cnt++] = id[c];
            }
        }
        const int nz = cnt;
        for (int j = 0; cnt < TOPK; j++) {
            bool used = false;
            for (int q2 = 0; q2 < nz; q2++)
                if (outv[q2] == j) { used = true; break; }
            if (!used) outv[cnt++] = j;
        }

        #pragma unroll
        for (int k = 0; k < TOPK; k++)
            out[(size_t)(row0 + r) * TOPK + k] = (float)outv[k];
    }
}

extern "C" void kernel_launch(void* const* d_in, const int* in_sizes, int n_in,
                              void* d_out, int out_size)
{
    const float* X = (const float*)d_in[0];
    const float* Y = (const float*)d_in[1];
    if (n_in >= 2 && in_sizes[0] == NY * KD && in_sizes[1] == NX * KD) {
        X = (const float*)d_in[1];
        Y = (const float*)d_in[0];
    }
    float* out = (float*)d_out;
    (void)out_size;

    static int attr_set = 0;
    if (!attr_set) {
        cudaFuncSetAttribute(snf_kernel, cudaFuncAttributeMaxDynamicSharedMemorySize,
                             SMEM_BYTES);
        attr_set = 1;
    }

    const int cvt_blocks = (NX * KD / 4 + NY * KD / 4 + 255) / 256;  // 12288
    cvt_kernel<<<cvt_blocks, 256>>>(X, Y);
    snf_kernel<<<NX / BM, THREADS, SMEM_BYTES>>>(X, Y, out);
}

// round 10
// speedup vs baseline: 4.8789x; 1.7727x over previous
#include <cuda_runtime.h>
#include <cuda_bf16.h>
#include <math.h>
#include <stdint.h>

#define NX 8192
#define NY 16384
#define KD 512
#define TOPK 16
#define CAND 24
#define CSTR 25

#define BM 64
#define BN 128
#define BK 32
#define THREADS 512
#define NSTAGES 2048            // (NY/BN) * (KD/BK)

#define NEG_INF __int_as_float(0xff800000)
#define EXP_LO   -87.3365478515625f
#define FLT_MIN_F 1.17549435082228751e-38f

// ---- smem byte layout ----
#define OFF_XS_B   0                       // bf16 Xs [64][520]          = 66,560
#define OFF_YS_B   66560                   // bf16 Ys [4][128][40]       = 40,960
#define OFF_SIM_B  107520                  // bf16 sim [64][136]         = 17,408 (reused as fp32 rv)
#define OFF_CV_B   124928                  // fp32 cv [CAND][64]         =  6,144
#define OFF_CI_B   131072                  // int  ci [CAND][64]         =  6,144
#define SMEM_BYTES 137216

#define XS_WSTRIDE 260    // words per Xs row
#define YS_WSTRIDE 20     // words per Ys row
#define YS_STAGE_B 10240
#define SIM_WSTRIDE 68
#define SIM_HSTRIDE 136

__device__ __nv_bfloat16 g_Xbf[(size_t)NX * KD];
__device__ __nv_bfloat16 g_Ybf[(size_t)NY * KD];

__global__ __launch_bounds__(256)
void cvt_kernel(const float* __restrict__ X, const float* __restrict__ Y)
{
    const size_t NXF4 = (size_t)NX * KD / 4;
    const size_t NYF4 = (size_t)NY * KD / 4;
    size_t i = (size_t)blockIdx.x * blockDim.x + threadIdx.x;
    if (i < NXF4) {
        float4 v = ((const float4*)X)[i];
        __nv_bfloat162 lo = __floats2bfloat162_rn(v.x, v.y);
        __nv_bfloat162 hi = __floats2bfloat162_rn(v.z, v.w);
        uint2 u = make_uint2(*(uint32_t*)&lo, *(uint32_t*)&hi);
        *(uint2*)&g_Xbf[i * 4] = u;
    } else if (i < NXF4 + NYF4) {
        size_t j = i - NXF4;
        float4 v = ((const float4*)Y)[j];
        __nv_bfloat162 lo = __floats2bfloat162_rn(v.x, v.y);
        __nv_bfloat162 hi = __floats2bfloat162_rn(v.z, v.w);
        uint2 u = make_uint2(*(uint32_t*)&lo, *(uint32_t*)&hi);
        *(uint2*)&g_Ybf[j * 4] = u;
    }
}

__device__ __forceinline__ uint32_t smem_u32(const void* p) {
    uint32_t a;
    asm("{ .reg .u64 t; cvta.to.shared.u64 t, %1; cvt.u32.u64 %0, t; }" : "=r"(a) : "l"(p));
    return a;
}
__device__ __forceinline__ void cp16(uint32_t dst, const void* src) {
    asm volatile("cp.async.cg.shared.global [%0], [%1], 16;\n" :: "r"(dst), "l"(src) : "memory");
}
__device__ __forceinline__ void hmma(float c[4], const uint32_t a[4],
                                     uint32_t b0, uint32_t b1)
{
    asm volatile(
        "mma.sync.aligned.m16n8k16.row.col.f32.bf16.bf16.f32 "
        "{%0,%1,%2,%3}, {%4,%5,%6,%7}, {%8,%9}, {%0,%1,%2,%3};"
        : "+f"(c[0]), "+f"(c[1]), "+f"(c[2]), "+f"(c[3])
        : "r"(a[0]), "r"(a[1]), "r"(a[2]), "r"(a[3]), "r"(b0), "r"(b1));
}

__global__ __launch_bounds__(THREADS, 1)
void snf_kernel(const float* __restrict__ X, const float* __restrict__ Y,
                float* __restrict__ out)
{
    extern __shared__ __align__(16) char smem[];
    uint32_t*       XsW  = (uint32_t*)(smem + OFF_XS_B);
    uint32_t*       simW = (uint32_t*)(smem + OFF_SIM_B);
    __nv_bfloat16*  simH = (__nv_bfloat16*)(smem + OFF_SIM_B);
    float*          rv   = (float*)(smem + OFF_SIM_B);
    float*          cv   = (float*)(smem + OFF_CV_B);
    int*            ci   = (int*)(smem + OFF_CI_B);

    const int tid  = threadIdx.x;
    const int warp = tid >> 5;
    const int lane = tid & 31;
    const int g    = lane >> 2;
    const int t    = lane & 3;
    const int mw   = warp & 3;     // m group (16 rows each)
    const int nw   = warp >> 2;    // n group (32 cols each)
    const int row0 = blockIdx.x * BM;
    const uint32_t sbase = smem_u32(smem);

    // ---- prologue: issue cp.async stages 0..2 ----
    #pragma unroll
    for (int ps = 0; ps < 3; ps++) {
        int jt1 = ps >> 4, kt1 = (ps & 15) * BK;   // ps<16 so jt1=0
        int n = tid >> 2, c = tid & 3;
        cp16(sbase + OFF_YS_B + ps * YS_STAGE_B + n * 80 + c * 16,
             g_Ybf + (size_t)(jt1 * BN + n) * KD + kt1 + c * 8);
        asm volatile("cp.async.commit_group;" ::: "memory");
    }

    // ---- fill bf16 Xs tile ----
    {
        const uint4* xsrc = (const uint4*)(g_Xbf + (size_t)row0 * KD);
        #pragma unroll
        for (int i = 0; i < 8; i++) {
            int f = tid + i * THREADS;   // 0..4095
            int m = f >> 6, c = f & 63;
            *(uint4*)(smem + OFF_XS_B + m * 1040 + c * 16) = xsrc[m * 64 + c];
        }
    }
    for (int i = tid; i < CAND * BM; i += THREADS) { cv[i] = NEG_INF; ci[i] = 0; }

    float acc[4][4];   // [nt][quad]

    for (int S = 0; S < NSTAGES; S++) {
        asm volatile("cp.async.wait_group 2;" ::: "memory");
        __syncthreads();

        // issue stage S+3 (buffer (S+3)&3; its old data was consumed at stage S-1)
        if (S + 3 < NSTAGES) {
            int ps = S + 3;
            int jt1 = ps >> 4, kt1 = (ps & 15) * BK;
            int n = tid >> 2, c = tid & 3;
            cp16(sbase + OFF_YS_B + (ps & 3) * YS_STAGE_B + n * 80 + c * 16,
                 g_Ybf + (size_t)(jt1 * BN + n) * KD + kt1 + c * 8);
        }
        asm volatile("cp.async.commit_group;" ::: "memory");

        // ---- compute stage S ----
        const uint32_t* YsW = (const uint32_t*)(smem + OFF_YS_B + (S & 3) * YS_STAGE_B);
        const int kb2 = (S & 15) * (BK / 2);

        if ((S & 15) == 0) {
            #pragma unroll
            for (int nt = 0; nt < 4; nt++)
                #pragma unroll
                for (int q = 0; q < 4; q++) acc[nt][q] = 0.0f;
        }

        #pragma unroll
        for (int ks = 0; ks < 2; ks++) {
            const int kw = ks * 8;
            uint32_t a[4];
            {
                int m0 = mw * 16;
                a[0] = XsW[(m0 + g) * XS_WSTRIDE + kb2 + kw + t];
                a[1] = XsW[(m0 + 8 + g) * XS_WSTRIDE + kb2 + kw + t];
                a[2] = XsW[(m0 + g) * XS_WSTRIDE + kb2 + kw + t + 4];
                a[3] = XsW[(m0 + 8 + g) * XS_WSTRIDE + kb2 + kw + t + 4];
            }
            #pragma unroll
            for (int nt = 0; nt < 4; nt++) {
                int n = nw * 32 + nt * 8 + g;
                uint32_t b0 = YsW[n * YS_WSTRIDE + kw + t];
                uint32_t b1 = YsW[n * YS_WSTRIDE + kw + t + 4];
                hmma(acc[nt], a, b0, b1);
            }
        }

        if ((S & 15) == 15) {
            const int jt = (S >> 4) * BN;
            // dump approx sims as bf16 pairs
            #pragma unroll
            for (int nt = 0; nt < 4; nt++) {
                int r0 = mw * 16 + g;
                int cw = nw * 16 + nt * 4 + t;    // word column
                __nv_bfloat162 p0 = __floats2bfloat162_rn(acc[nt][0], acc[nt][1]);
                __nv_bfloat162 p1 = __floats2bfloat162_rn(acc[nt][2], acc[nt][3]);
                simW[(r0 + 0) * SIM_WSTRIDE + cw] = *(uint32_t*)&p0;
                simW[(r0 + 8) * SIM_WSTRIDE + cw] = *(uint32_t*)&p1;
            }
            __syncthreads();

            // candidate scan: warp w owns rows 4w..4w+3
            #pragma unroll
            for (int rr = 0; rr < 4; rr++) {
                const int r = warp * 4 + rr;
                float v[4]; int jj[4];
                #pragma unroll
                for (int c = 0; c < 4; c++) {
                    v[c]  = __bfloat162float(simH[r * SIM_HSTRIDE + lane + c * 32]);
                    jj[c] = jt + lane + c * 32;
                }
                while (true) {
                    float thr = cv[(CAND - 1) * BM + r];
                    bool any = (v[0] > thr) | (v[1] > thr) | (v[2] > thr) | (v[3] > thr);
                    if (!__ballot_sync(0xffffffffu, any)) break;
                    float bmv = NEG_INF; int bj = 0x7fffffff;
                    #pragma unroll
                    for (int c = 0; c < 4; c++)
                        if (v[c] > thr && (v[c] > bmv || (v[c] == bmv && jj[c] < bj))) {
                            bmv = v[c]; bj = jj[c];
                        }
                    #pragma unroll
                    for (int off = 16; off > 0; off >>= 1) {
                        float ov = __shfl_xor_sync(0xffffffffu, bmv, off);
                        int   oj = __shfl_xor_sync(0xffffffffu, bj,  off);
                        if (ov > bmv || (ov == bmv && oj < bj)) { bmv = ov; bj = oj; }
                    }
                    if (lane == 0) {
                        int p = CAND - 1;
                        while (p > 0 && bmv > cv[(p - 1) * BM + r]) {
                            cv[p * BM + r] = cv[(p - 1) * BM + r];
                            ci[p * BM + r] = ci[(p - 1) * BM + r];
                            p--;
                        }
                        cv[p * BM + r] = bmv; ci[p * BM + r] = bj;
                    }
                    __syncwarp();
                    #pragma unroll
                    for (int c = 0; c < 4; c++)
                        if (v[c] == bmv && jj[c] == bj) v[c] = NEG_INF;
                }
            }
        }
    }
    __syncthreads();

    // ---- EXACT rescore: sequential-k fp32 fmaf chain (bit-identical to ref) ----
    {
        float acc3[3];
        int   mloc[3], cloc[3];
        const float4* xp[3];
        const float4* yp[3];
        #pragma unroll
        for (int d = 0; d < 3; d++) {
            int idx = tid + d * THREADS;        // 0..1535 = CAND*BM-1
            int m = idx / CAND, c = idx % CAND;
            mloc[d] = m; cloc[d] = c;
            xp[d] = (const float4*)(X + (size_t)(row0 + m) * KD);
            yp[d] = (const float4*)(Y + (size_t)ci[c * BM + m] * KD);
            acc3[d] = 0.0f;
        }
        for (int k4 = 0; k4 < KD / 4; k4++) {
            #pragma unroll
            for (int d = 0; d < 3; d++) {
                float4 x4 = __ldg(xp[d] + k4);
                float4 y4 = __ldg(yp[d] + k4);
                float a = acc3[d];
                a = fmaf(x4.x, y4.x, a);
                a = fmaf(x4.y, y4.y, a);
                a = fmaf(x4.z, y4.z, a);
                a = fmaf(x4.w, y4.w, a);
                acc3[d] = a;
            }
        }
        __syncthreads();   // scan reads of sim done; area becomes rv
        #pragma unroll
        for (int d = 0; d < 3; d++)
            rv[mloc[d] * CSTR + cloc[d]] = __fdiv_rn(acc3[d], 0.07f);
    }
    __syncthreads();

    // ---- exact FTZ-softmax epilogue (unchanged passing rule) ----
    if (tid < BM) {
        const int r = tid;
        float pv[CAND]; int id[CAND];
        #pragma unroll
        for (int c = 0; c < CAND; c++) { pv[c] = rv[r * CSTR + c]; id[c] = ci[c * BM + r]; }

        for (int i = 1; i < CAND; i++) {
            float kp = pv[i]; int kd = id[i];
            int j2 = i - 1;
            while (j2 >= 0 && (pv[j2] < kp || (pv[j2] == kp && id[j2] > kd))) {
                pv[j2 + 1] = pv[j2]; id[j2 + 1] = id[j2];
                j2--;
            }
            pv[j2 + 1] = kp; id[j2 + 1] = kd;
        }

        const float M = pv[0];
        float ef[CAND]; float S = 0.0f;
        #pragma unroll
        for (int c = 0; c < CAND; c++) {
            float d = pv[c] - M;
            float e = 0.0f;
            if (d > EXP_LO) {
                e = __double2float_rn(exp((double)d));
                if (e < FLT_MIN_F) e = 0.0f;
            }
            ef[c] = e;
            S += e;
        }

        int outv[TOPK]; int cnt = 0;
        for (int c = 0; c < CAND && cnt < TOPK; c++) {
            if (ef[c] > 0.0f) {
                float q = __fdiv_rn(ef[c], S);
                if (q >= FLT_MIN_F) outv[cnt++] = id[c];
            }
        }
        const int nz = cnt;
        for (int j = 0; cnt < TOPK; j++) {
            bool used = false;
            for (int q2 = 0; q2 < nz; q2++)
                if (outv[q2] == j) { used = true; break; }
            if (!used) outv[cnt++] = j;
        }

        #pragma unroll
        for (int k = 0; k < TOPK; k++)
            out[(size_t)(row0 + r) * TOPK + k] = (float)outv[k];
    }
}

extern "C" void kernel_launch(void* const* d_in, const int* in_sizes, int n_in,
                              void* d_out, int out_size)
{
    const float* X = (const float*)d_in[0];
    const float* Y = (const float*)d_in[1];
    if (n_in >= 2 && in_sizes[0] == NY * KD && in_sizes[1] == NX * KD) {
        X = (const float*)d_in[1];
        Y = (const float*)d_in[0];
    }
    float* out = (float*)d_out;
    (void)out_size;

    static int attr_set = 0;
    if (!attr_set) {
        cudaFuncSetAttribute(snf_kernel, cudaFuncAttributeMaxDynamicSharedMemorySize,
                             SMEM_BYTES);
        attr_set = 1;
    }

    const int cvt_blocks = (NX * KD / 4 + NY * KD / 4 + 255) / 256;
    cvt_kernel<<<cvt_blocks, 256>>>(X, Y);
    snf_kernel<<<NX / BM, THREADS, SMEM_BYTES>>>(X, Y, out);
}

// round 11
// speedup vs baseline: 5.4534x; 1.1178x over previous
#include <cuda_runtime.h>
#include <cuda_bf16.h>
#include <math.h>
#include <stdint.h>

#define NX 8192
#define NY 16384
#define KD 512
#define TOPK 16
#define CAND 24
#define CSTR 25

#define BM 64
#define BN 128
#define BK 64
#define THREADS 512
#define NSTAGES 1024            // (NY/BN) * (KD/BK)

#define NEG_INF __int_as_float(0xff800000)
#define EXP_LO   -87.3365478515625f
#define FLT_MIN_F 1.17549435082228751e-38f

// ---- smem byte layout ----
#define OFF_XS_B   0                       // bf16 Xs [64][520]          = 66,560
#define OFF_YS_B   66560                   // bf16 Ys [3][128][72]       = 55,296
#define OFF_SIM_B  121856                  // bf16 sim [64][136]         = 17,408 (reused fp32 rv)
#define OFF_CV_B   139264                  // fp32 cv [CAND][64]         =  6,144
#define OFF_CI_B   145408                  // int  ci [CAND][64]         =  6,144
#define SMEM_BYTES 151552

#define XS_RSTRIDE_B 1040    // bytes per Xs row (520 halves)
#define YS_RSTRIDE_B 144     // bytes per Ys row (72 halves)
#define YS_STAGE_B   18432   // 128 * 144
#define SIM_WSTRIDE  68
#define SIM_HSTRIDE  136

__device__ __nv_bfloat16 g_Xbf[(size_t)NX * KD];
__device__ __nv_bfloat16 g_Ybf[(size_t)NY * KD];

__global__ __launch_bounds__(256)
void cvt_kernel(const float* __restrict__ X, const float* __restrict__ Y)
{
    const size_t NXF4 = (size_t)NX * KD / 4;
    const size_t NYF4 = (size_t)NY * KD / 4;
    size_t i = (size_t)blockIdx.x * blockDim.x + threadIdx.x;
    if (i < NXF4) {
        float4 v = ((const float4*)X)[i];
        __nv_bfloat162 lo = __floats2bfloat162_rn(v.x, v.y);
        __nv_bfloat162 hi = __floats2bfloat162_rn(v.z, v.w);
        uint2 u = make_uint2(*(uint32_t*)&lo, *(uint32_t*)&hi);
        *(uint2*)&g_Xbf[i * 4] = u;
    } else if (i < NXF4 + NYF4) {
        size_t j = i - NXF4;
        float4 v = ((const float4*)Y)[j];
        __nv_bfloat162 lo = __floats2bfloat162_rn(v.x, v.y);
        __nv_bfloat162 hi = __floats2bfloat162_rn(v.z, v.w);
        uint2 u = make_uint2(*(uint32_t*)&lo, *(uint32_t*)&hi);
        *(uint2*)&g_Ybf[j * 4] = u;
    }
}

__device__ __forceinline__ uint32_t smem_u32(const void* p) {
    uint32_t a;
    asm("{ .reg .u64 t; cvta.to.shared.u64 t, %1; cvt.u32.u64 %0, t; }" : "=r"(a) : "l"(p));
    return a;
}
__device__ __forceinline__ void cp16(uint32_t dst, const void* src) {
    asm volatile("cp.async.cg.shared.global [%0], [%1], 16;\n" :: "r"(dst), "l"(src) : "memory");
}
__device__ __forceinline__ void ldsm_x4(uint32_t& r0, uint32_t& r1, uint32_t& r2, uint32_t& r3,
                                        uint32_t addr)
{
    asm volatile("ldmatrix.sync.aligned.m8n8.x4.shared.b16 {%0,%1,%2,%3}, [%4];"
                 : "=r"(r0), "=r"(r1), "=r"(r2), "=r"(r3) : "r"(addr));
}
__device__ __forceinline__ void hmma(float c[4], const uint32_t a[4],
                                     uint32_t b0, uint32_t b1)
{
    asm volatile(
        "mma.sync.aligned.m16n8k16.row.col.f32.bf16.bf16.f32 "
        "{%0,%1,%2,%3}, {%4,%5,%6,%7}, {%8,%9}, {%0,%1,%2,%3};"
        : "+f"(c[0]), "+f"(c[1]), "+f"(c[2]), "+f"(c[3])
        : "r"(a[0]), "r"(a[1]), "r"(a[2]), "r"(a[3]), "r"(b0), "r"(b1));
}

__global__ __launch_bounds__(THREADS, 1)
void snf_kernel(const float* __restrict__ X, const float* __restrict__ Y,
                float* __restrict__ out)
{
    extern __shared__ __align__(16) char smem[];
    uint32_t*       simW = (uint32_t*)(smem + OFF_SIM_B);
    __nv_bfloat16*  simH = (__nv_bfloat16*)(smem + OFF_SIM_B);
    float*          rv   = (float*)(smem + OFF_SIM_B);
    float*          cv   = (float*)(smem + OFF_CV_B);
    int*            ci   = (int*)(smem + OFF_CI_B);

    const int tid  = threadIdx.x;
    const int warp = tid >> 5;
    const int lane = tid & 31;
    const int g    = lane >> 2;
    const int t    = lane & 3;
    const int mw   = warp & 3;     // m group (16 rows)
    const int nw   = warp >> 2;    // n group (32 cols)
    const int row0 = blockIdx.x * BM;
    const uint32_t sbase = smem_u32(smem);

    // per-lane LDSM addresses (hoisted; only +const per stage)
    // A x4: lanes 0-15 -> rows m0..15 @k0(16B), lanes 16-31 -> same rows @k8(+16B)
    const uint32_t aLane = sbase + OFF_XS_B
        + (uint32_t)(mw * 16 + (lane & 15)) * XS_RSTRIDE_B + ((lane >> 4) << 4);
    // B x4 (two n-tiles per ldsm): lanes0-7 nt_a@k0, 8-15 nt_a@k8, 16-23 nt_b@k0, 24-31 nt_b@k8
    const uint32_t bLane = (uint32_t)(nw * 32 + ((lane >> 4) & 1) * 8 + (lane & 7)) * YS_RSTRIDE_B
        + (((lane >> 3) & 1) << 4);

    // ---- prologue: issue cp.async stages 0,1 ----
    #pragma unroll
    for (int ps = 0; ps < 2; ps++) {
        int kt1 = ps * BK;            // jt=0 for ps<8
        #pragma unroll
        for (int s2 = 0; s2 < 2; s2++) {
            int ch = tid + s2 * THREADS;   // 0..1023
            int n = ch >> 3, c = ch & 7;
            cp16(sbase + OFF_YS_B + ps * YS_STAGE_B + n * YS_RSTRIDE_B + c * 16,
                 g_Ybf + (size_t)n * KD + kt1 + c * 8);
        }
        asm volatile("cp.async.commit_group;" ::: "memory");
    }

    // ---- fill bf16 Xs tile ----
    {
        const uint4* xsrc = (const uint4*)(g_Xbf + (size_t)row0 * KD);
        #pragma unroll
        for (int i = 0; i < 8; i++) {
            int f = tid + i * THREADS;   // 0..4095
            int m = f >> 6, c = f & 63;
            *(uint4*)(smem + OFF_XS_B + m * XS_RSTRIDE_B + c * 16) = xsrc[m * 64 + c];
        }
    }
    for (int i = tid; i < CAND * BM; i += THREADS) { cv[i] = NEG_INF; ci[i] = 0; }

    float acc[4][4];   // [nt][quad]
    int cbuf = 0, ibuf = 2;

    for (int S = 0; S < NSTAGES; S++) {
        asm volatile("cp.async.wait_group 1;" ::: "memory");
        __syncthreads();

        // issue stage S+2 into buffer ibuf (its old contents consumed at stage S-1)
        if (S + 2 < NSTAGES) {
            int ps = S + 2;
            int jt1 = ps >> 3, kt1 = (ps & 7) * BK;
            uint32_t dstb = sbase + OFF_YS_B + ibuf * YS_STAGE_B;
            const __nv_bfloat16* srcb = g_Ybf + (size_t)jt1 * BN * KD + kt1;
            #pragma unroll
            for (int s2 = 0; s2 < 2; s2++) {
                int ch = tid + s2 * THREADS;
                int n = ch >> 3, c = ch & 7;
                cp16(dstb + n * YS_RSTRIDE_B + c * 16, srcb + (size_t)n * KD + c * 8);
            }
        }
        asm volatile("cp.async.commit_group;" ::: "memory");

        // ---- compute stage S from buffer cbuf ----
        const uint32_t aStage = aLane + (uint32_t)(S & 7) * (BK * 2);  // 128 B per stage
        const uint32_t bStage = sbase + OFF_YS_B + cbuf * YS_STAGE_B + bLane;

        if ((S & 7) == 0) {
            #pragma unroll
            for (int nt = 0; nt < 4; nt++)
                #pragma unroll
                for (int q = 0; q < 4; q++) acc[nt][q] = 0.0f;
        }

        #pragma unroll
        for (int ks = 0; ks < 4; ks++) {
            uint32_t a[4];
            ldsm_x4(a[0], a[1], a[2], a[3], aStage + ks * 32);
            uint32_t b0, b1, b2, b3, b4, b5, b6, b7;
            ldsm_x4(b0, b1, b2, b3, bStage + ks * 32);                 // nt 0,1
            ldsm_x4(b4, b5, b6, b7, bStage + 16 * YS_RSTRIDE_B + ks * 32); // nt 2,3
            hmma(acc[0], a, b0, b1);
            hmma(acc[1], a, b2, b3);
            hmma(acc[2], a, b4, b5);
            hmma(acc[3], a, b6, b7);
        }

        if ((S & 7) == 7) {
            const int jt = (S >> 3) * BN;
            // dump approx sims as bf16 pairs
            #pragma unroll
            for (int nt = 0; nt < 4; nt++) {
                int r0 = mw * 16 + g;
                int cw = nw * 16 + nt * 4 + t;
                __nv_bfloat162 p0 = __floats2bfloat162_rn(acc[nt][0], acc[nt][1]);
                __nv_bfloat162 p1 = __floats2bfloat162_rn(acc[nt][2], acc[nt][3]);
                simW[(r0 + 0) * SIM_WSTRIDE + cw] = *(uint32_t*)&p0;
                simW[(r0 + 8) * SIM_WSTRIDE + cw] = *(uint32_t*)&p1;
            }
            __syncthreads();

            // candidate scan: warp w owns rows 4w..4w+3
            #pragma unroll
            for (int rr = 0; rr < 4; rr++) {
                const int r = warp * 4 + rr;
                float v[4]; int jj[4];
                #pragma unroll
                for (int c = 0; c < 4; c++) {
                    v[c]  = __bfloat162float(simH[r * SIM_HSTRIDE + lane + c * 32]);
                    jj[c] = jt + lane + c * 32;
                }
                while (true) {
                    float thr = cv[(CAND - 1) * BM + r];
                    bool any = (v[0] > thr) | (v[1] > thr) | (v[2] > thr) | (v[3] > thr);
                    if (!__ballot_sync(0xffffffffu, any)) break;
                    float bmv = NEG_INF; int bj = 0x7fffffff;
                    #pragma unroll
                    for (int c = 0; c < 4; c++)
                        if (v[c] > thr && (v[c] > bmv || (v[c] == bmv && jj[c] < bj))) {
                            bmv = v[c]; bj = jj[c];
                        }
                    #pragma unroll
                    for (int off = 16; off > 0; off >>= 1) {
                        float ov = __shfl_xor_sync(0xffffffffu, bmv, off);
                        int   oj = __shfl_xor_sync(0xffffffffu, bj,  off);
                        if (ov > bmv || (ov == bmv && oj < bj)) { bmv = ov; bj = oj; }
                    }
                    if (lane == 0) {
                        int p = CAND - 1;
                        while (p > 0 && bmv > cv[(p - 1) * BM + r]) {
                            cv[p * BM + r] = cv[(p - 1) * BM + r];
                            ci[p * BM + r] = ci[(p - 1) * BM + r];
                            p--;
                        }
                        cv[p * BM + r] = bmv; ci[p * BM + r] = bj;
                    }
                    __syncwarp();
                    #pragma unroll
                    for (int c = 0; c < 4; c++)
                        if (v[c] == bmv && jj[c] == bj) v[c] = NEG_INF;
                }
            }
        }

        cbuf = (cbuf == 2) ? 0 : cbuf + 1;
        ibuf = (ibuf == 2) ? 0 : ibuf + 1;
    }
    __syncthreads();

    // ---- EXACT rescore: sequential-k fp32 fmaf chain (bit-identical to ref) ----
    {
        float acc3[3];
        int   mloc[3], cloc[3];
        const float4* xp[3];
        const float4* yp[3];
        #pragma unroll
        for (int d = 0; d < 3; d++) {
            int idx = tid + d * THREADS;        // 0..1535 = CAND*BM-1
            int m = idx / CAND, c = idx % CAND;
            mloc[d] = m; cloc[d] = c;
            xp[d] = (const float4*)(X + (size_t)(row0 + m) * KD);
            yp[d] = (const float4*)(Y + (size_t)ci[c * BM + m] * KD);
            acc3[d] = 0.0f;
        }
        for (int k4 = 0; k4 < KD / 4; k4++) {
            #pragma unroll
            for (int d = 0; d < 3; d++) {
                float4 x4 = __ldg(xp[d] + k4);
                float4 y4 = __ldg(yp[d] + k4);
                float a = acc3[d];
                a = fmaf(x4.x, y4.x, a);
                a = fmaf(x4.y, y4.y, a);
                a = fmaf(x4.z, y4.z, a);
                a = fmaf(x4.w, y4.w, a);
                acc3[d] = a;
            }
        }
        __syncthreads();   // scan reads of sim done; area becomes rv
        #pragma unroll
        for (int d = 0; d < 3; d++)
            rv[mloc[d] * CSTR + cloc[d]] = __fdiv_rn(acc3[d], 0.07f);
    }
    __syncthreads();

    // ---- exact FTZ-softmax epilogue (unchanged passing rule) ----
    if (tid < BM) {
        const int r = tid;
        float pv[CAND]; int id[CAND];
        #pragma unroll
        for (int c = 0; c < CAND; c++) { pv[c] = rv[r * CSTR + c]; id[c] = ci[c * BM + r]; }

        for (int i = 1; i < CAND; i++) {
            float kp = pv[i]; int kd = id[i];
            int j2 = i - 1;
            while (j2 >= 0 && (pv[j2] < kp || (pv[j2] == kp && id[j2] > kd))) {
                pv[j2 + 1] = pv[j2]; id[j2 + 1] = id[j2];
                j2--;
            }
            pv[j2 + 1] = kp; id[j2 + 1] = kd;
        }

        const float M = pv[0];
        float ef[CAND]; float S = 0.0f;
        #pragma unroll
        for (int c = 0; c < CAND; c++) {
            float d = pv[c] - M;
            float e = 0.0f;
            if (d > EXP_LO) {
                e = __double2float_rn(exp((double)d));
                if (e < FLT_MIN_F) e = 0.0f;
            }
            ef[c] = e;
            S += e;
        }

        int outv[TOPK]; int cnt = 0;
        for (int c = 0; c < CAND && cnt < TOPK; c++) {
            if (ef[c] > 0.0f) {
                float q = __fdiv_rn(ef[c], S);
                if (q >= FLT_MIN_F) outv[cnt++] = id[c];
            }
        }
        const int nz = cnt;
        for (int j = 0; cnt < TOPK; j++) {
            bool used = false;
            for (int q2 = 0; q2 < nz; q2++)
                if (outv[q2] == j) { used = true; break; }
            if (!used) outv[cnt++] = j;
        }

        #pragma unroll
        for (int k = 0; k < TOPK; k++)
            out[(size_t)(row0 + r) * TOPK + k] = (float)outv[k];
    }
}

extern "C" void kernel_launch(void* const* d_in, const int* in_sizes, int n_in,
                              void* d_out, int out_size)
{
    const float* X = (const float*)d_in[0];
    const float* Y = (const float*)d_in[1];
    if (n_in >= 2 && in_sizes[0] == NY * KD && in_sizes[1] == NX * KD) {
        X = (const float*)d_in[1];
        Y = (const float*)d_in[0];
    }
    float* out = (float*)d_out;
    (void)out_size;

    static int attr_set = 0;
    if (!attr_set) {
        cudaFuncSetAttribute(snf_kernel, cudaFuncAttributeMaxDynamicSharedMemorySize,
                             SMEM_BYTES);
        attr_set = 1;
    }

    const int cvt_blocks = (NX * KD / 4 + NY * KD / 4 + 255) / 256;
    cvt_kernel<<<cvt_blocks, 256>>>(X, Y);
    snf_kernel<<<NX / BM, THREADS, SMEM_BYTES>>>(X, Y, out);
}